// round 13
// baseline (speedup 1.0000x reference)
#include <cuda_runtime.h>
#include <cuda_bf16.h>
#include <math.h>
#include <stdint.h>

#define NB   32
#define NC   512
#define NHW  1024
#define NOUT 256
#define EPSV 1e-5f
#define BKF  32                  // K elements per stage
#define WB   20                  // SMEM words (4B) per 32-bf16 row (pad to 80B)
#define TILE_W (128 * WB)        // 2560 words per 128xBKF bf16 tile
#define BUF_W  (4 * TILE_W)      // Ahi,Alo,Bhi,Blo per stage buffer
#define SMEM_BYTES (2 * BUF_W * 4)   // 81920 B

// ----------------------------- scratch -------------------------------------
__device__ float g_tp[NB][2*NOUT][NC];          // theta [0,256), phi [256,512)
__device__ float g_uvpart[NB][2*NOUT][16];      // w4-weighted row partials
__device__ float g_xepart[NB][NC][32];
__device__ float g_cpart[NB][NC][8];
__device__ __nv_bfloat16 g_xhi[(size_t)NB*NC*NHW];   // x split, [b][c][hw]
__device__ __nv_bfloat16 g_xlo[(size_t)NB*NC*NHW];
__device__ __nv_bfloat16 g_xThi[(size_t)NB*NHW*NC];  // x^T split, [b][hw][c]
__device__ __nv_bfloat16 g_xTlo[(size_t)NB*NHW*NC];
__device__ __nv_bfloat16 g_w12hi[2*NOUT*NHW];        // concat(w1,w2) split
__device__ __nv_bfloat16 g_w12lo[2*NOUT*NHW];
__device__ __nv_bfloat16 g_w3hi[NC*NC];
__device__ __nv_bfloat16 g_w3lo[NC*NC];

extern __shared__ uint32_t dynw[];

// ----------------------------- PTX helpers ---------------------------------
__device__ __forceinline__ uint32_t smem_u32(const void* p) {
    uint32_t a;
    asm("{ .reg .u64 t; cvta.to.shared.u64 t, %1; cvt.u32.u64 %0, t; }" : "=r"(a) : "l"(p));
    return a;
}
__device__ __forceinline__ void cpa16(uint32_t dst, const void* src) {
    asm volatile("cp.async.cg.shared.global [%0], [%1], 16;" :: "r"(dst), "l"(src));
}
__device__ __forceinline__ void cpa_commit() { asm volatile("cp.async.commit_group;"); }
template<int N> __device__ __forceinline__ void cpa_wait() {
    asm volatile("cp.async.wait_group %0;" :: "n"(N));
}
// D(16x8) += A(16x16) * B^T, bf16 inputs, fp32 accum
__device__ __forceinline__ void mma16(float* c, const uint32_t* a, const uint32_t* b) {
    asm volatile("mma.sync.aligned.m16n8k16.row.col.f32.bf16.bf16.f32 "
        "{%0,%1,%2,%3}, {%4,%5,%6,%7}, {%8,%9}, {%0,%1,%2,%3};"
        : "+f"(c[0]), "+f"(c[1]), "+f"(c[2]), "+f"(c[3])
        : "r"(a[0]), "r"(a[1]), "r"(a[2]), "r"(a[3]), "r"(b[0]), "r"(b[1]));
}
__device__ __forceinline__ void split2(float a, float b,
                                       __nv_bfloat162& h, __nv_bfloat162& l) {
    __nv_bfloat16 ha = __float2bfloat16(a), hb = __float2bfloat16(b);
    __nv_bfloat16 la = __float2bfloat16(a - __bfloat162float(ha));
    __nv_bfloat16 lb = __float2bfloat16(b - __bfloat162float(hb));
    h = __halves2bfloat162(ha, hb);
    l = __halves2bfloat162(la, lb);
}

// Async-copy a 128x32 bf16 tile (row stride ld elems) into padded SMEM tile.
__device__ __forceinline__ void load_tile_bf(uint32_t sb, int woff,
        const __nv_bfloat16* __restrict__ src, int ld, int k0, int tid) {
    #pragma unroll
    for (int i = 0; i < 2; i++) {
        const int c = tid + i * 256;      // 512 chunks of 16B
        const int row = c >> 2;
        const int q = c & 3;
        cpa16(sb + (uint32_t)(woff + row * WB) * 4u + q * 16,
              src + (size_t)row * ld + k0 + q * 8);
    }
}

// One BK=32 stage: 3-term bf16 MMAs; warp computes 64x32.
__device__ __forceinline__ void stage_mma(const uint32_t* __restrict__ Ah,
                                          const uint32_t* __restrict__ Al,
                                          const uint32_t* __restrict__ Bh,
                                          const uint32_t* __restrict__ Bl,
                                          int mb, int nb, int g, int tg,
                                          float (&acc)[4][4][4]) {
    #pragma unroll
    for (int ks = 0; ks < 2; ks++) {
        const int kw = ks * 8;
        uint32_t bh[4][2], bl[4][2];
        #pragma unroll
        for (int nf = 0; nf < 4; nf++) {
            const int base = (nb + nf * 8 + g) * WB + kw;
            bh[nf][0] = Bh[base + tg];  bh[nf][1] = Bh[base + 4 + tg];
            bl[nf][0] = Bl[base + tg];  bl[nf][1] = Bl[base + 4 + tg];
        }
        #pragma unroll
        for (int mf = 0; mf < 4; mf++) {
            const int r0 = (mb + mf * 16 + g) * WB + kw;
            const int r1 = r0 + 8 * WB;
            uint32_t ah[4] = {Ah[r0 + tg], Ah[r1 + tg], Ah[r0 + 4 + tg], Ah[r1 + 4 + tg]};
            uint32_t al[4] = {Al[r0 + tg], Al[r1 + tg], Al[r0 + 4 + tg], Al[r1 + 4 + tg]};
            #pragma unroll
            for (int nf = 0; nf < 4; nf++) {
                mma16(acc[mf][nf], ah, bh[nf]);
                mma16(acc[mf][nf], ah, bl[nf]);
                mma16(acc[mf][nf], al, bh[nf]);
            }
        }
    }
}

// Double-buffered mainloop: D[128,128] += A[128,K] * B[128,K]^T
template<int KSTEPS>
__device__ __forceinline__ void gemm_main(uint32_t sb, const uint32_t* smw,
        const __nv_bfloat16* __restrict__ Ahi, const __nv_bfloat16* __restrict__ Alo, int lda,
        const __nv_bfloat16* __restrict__ Bhi, const __nv_bfloat16* __restrict__ Blo, int ldb,
        int tid, int mb, int nb, int g, int tg, float (&acc)[4][4][4]) {
    load_tile_bf(sb, 0,          Ahi, lda, 0, tid);
    load_tile_bf(sb, TILE_W,     Alo, lda, 0, tid);
    load_tile_bf(sb, 2 * TILE_W, Bhi, ldb, 0, tid);
    load_tile_bf(sb, 3 * TILE_W, Blo, ldb, 0, tid);
    cpa_commit();
    for (int s = 0; s < KSTEPS; s++) {
        const int cur = s & 1;
        if (s + 1 < KSTEPS) {
            const int nw_ = ((s + 1) & 1) * BUF_W;
            const int k1 = (s + 1) * BKF;
            load_tile_bf(sb, nw_,              Ahi, lda, k1, tid);
            load_tile_bf(sb, nw_ + TILE_W,     Alo, lda, k1, tid);
            load_tile_bf(sb, nw_ + 2 * TILE_W, Bhi, ldb, k1, tid);
            load_tile_bf(sb, nw_ + 3 * TILE_W, Blo, ldb, k1, tid);
            cpa_commit();
            cpa_wait<1>();
        } else {
            cpa_wait<0>();
        }
        __syncthreads();
        const uint32_t* base = smw + cur * BUF_W;
        stage_mma(base, base + TILE_W, base + 2 * TILE_W, base + 3 * TILE_W,
                  mb, nb, g, tg, acc);
        __syncthreads();
    }
}

// ---------------------------------------------------------------------------
// P0: split weights into bf16 hi/lo
// ---------------------------------------------------------------------------
__global__ __launch_bounds__(256) void k_split_w(
    const float* __restrict__ w1, const float* __restrict__ w2,
    const float* __restrict__ w3)
{
    const int idx = blockIdx.x * 256 + threadIdx.x;
    const int N12 = 2 * NOUT * NHW;                  // 524288
    if (idx < N12) {
        float v = (idx < NOUT * NHW) ? w1[idx] : w2[idx - NOUT * NHW];
        __nv_bfloat16 h = __float2bfloat16(v);
        g_w12hi[idx] = h;
        g_w12lo[idx] = __float2bfloat16(v - __bfloat162float(h));
    } else {
        const int j = idx - N12;
        if (j < NC * NC) {
            float v = w3[j];
            __nv_bfloat16 h = __float2bfloat16(v);
            g_w3hi[j] = h;
            g_w3lo[j] = __float2bfloat16(v - __bfloat162float(h));
        }
    }
}

// ---------------------------------------------------------------------------
// P1: split x into bf16 hi/lo in BOTH layouts ([c][hw] and [hw][c])
// ---------------------------------------------------------------------------
__global__ __launch_bounds__(256) void k_split_x(const float* __restrict__ x)
{
    __shared__ float t[32][33];
    const int b = blockIdx.z;
    const int h0 = blockIdx.x * 32, c0 = blockIdx.y * 32;
    const int tid = threadIdx.x;
    const int tx = tid & 31, ty = tid >> 5;
    #pragma unroll
    for (int i = 0; i < 4; i++) {
        const int r = ty + i * 8;
        t[r][tx] = x[((size_t)b * NC + c0 + r) * NHW + h0 + tx];
    }
    __syncthreads();
    const int jr = tid >> 4;      // 0..15
    const int jc = tid & 15;      // pair index
    #pragma unroll
    for (int pass = 0; pass < 2; pass++) {
        const int r = jr + pass * 16;
        // non-transposed: row = c, pairs along hw
        {
            __nv_bfloat162 h, l;
            split2(t[r][2*jc], t[r][2*jc + 1], h, l);
            const size_t base = (((size_t)b * NC + c0 + r) * NHW + h0) >> 1;
            ((__nv_bfloat162*)g_xhi)[base + jc] = h;
            ((__nv_bfloat162*)g_xlo)[base + jc] = l;
        }
        // transposed: row = hw, pairs along c
        {
            __nv_bfloat162 h, l;
            split2(t[2*jc][r], t[2*jc + 1][r], h, l);
            const size_t base = (((size_t)b * NHW + h0 + r) * NC + c0) >> 1;
            ((__nv_bfloat162*)g_xThi)[base + jc] = h;
            ((__nv_bfloat162*)g_xTlo)[base + jc] = l;
        }
    }
}

// ---------------------------------------------------------------------------
// K1: theta/phi GEMM (3-term bf16) + BN + ReLU + fused u/v partials.
// grid (cn=4, om=4, b=32), 256 threads.
// ---------------------------------------------------------------------------
__global__ __launch_bounds__(256) void k_mma_tp(
    const float* __restrict__ b1, const float* __restrict__ g1,
    const float* __restrict__ be1, const float* __restrict__ m1,
    const float* __restrict__ v1,
    const float* __restrict__ b2, const float* __restrict__ g2,
    const float* __restrict__ be2, const float* __restrict__ m2,
    const float* __restrict__ v2, const float* __restrict__ w4)
{
    const uint32_t* smw = dynw;
    const uint32_t sb = smem_u32(smw);
    const int tid = threadIdx.x, lane = tid & 31, w = tid >> 5;
    const int mw = w & 1, nw = w >> 1;
    const int g = lane >> 2, tg = lane & 3;
    const int mb = mw * 64, nb = nw * 32;
    const int b = blockIdx.z, om0 = blockIdx.y * 128, cn0 = blockIdx.x * 128;

    float acc[4][4][4];
    #pragma unroll
    for (int i = 0; i < 4; i++)
        #pragma unroll
        for (int j = 0; j < 4; j++)
            #pragma unroll
            for (int q = 0; q < 4; q++) acc[i][j][q] = 0.f;

    const __nv_bfloat16* Ah = g_w12hi + (size_t)om0 * NHW;
    const __nv_bfloat16* Al = g_w12lo + (size_t)om0 * NHW;
    const __nv_bfloat16* Bh = g_xhi + ((size_t)b * NC + cn0) * NHW;
    const __nv_bfloat16* Bl = g_xlo + ((size_t)b * NC + cn0) * NHW;

    gemm_main<NHW / BKF>(sb, smw, Ah, Al, NHW, Bh, Bl, NHW, tid, mb, nb, g, tg, acc);

    // w4 weight for u/v partial: theta rows -> w4[1+NC+c] (v), phi rows -> w4[1+c] (u)
    const float* wsel = (om0 < NOUT) ? (w4 + 1 + NC) : (w4 + 1);
    const int slot = blockIdx.x * 4 + nw;

    #pragma unroll
    for (int mf = 0; mf < 4; mf++) {
        const int o0 = om0 + mb + mf * 16 + g;
        const int o1 = o0 + 8;
        float sc0, bp0, sc1, bp1;
        if (om0 < NOUT) {
            sc0 = g1[o0] * rsqrtf(v1[o0] + EPSV);
            bp0 = (b1[o0] - m1[o0]) * sc0 + be1[o0];
            sc1 = g1[o1] * rsqrtf(v1[o1] + EPSV);
            bp1 = (b1[o1] - m1[o1]) * sc1 + be1[o1];
        } else {
            const int p0 = o0 - NOUT, p1 = o1 - NOUT;
            sc0 = g2[p0] * rsqrtf(v2[p0] + EPSV);
            bp0 = (b2[p0] - m2[p0]) * sc0 + be2[p0];
            sc1 = g2[p1] * rsqrtf(v2[p1] + EPSV);
            bp1 = (b2[p1] - m2[p1]) * sc1 + be2[p1];
        }
        float up0 = 0.f, up1 = 0.f;
        #pragma unroll
        for (int nf = 0; nf < 4; nf++) {
            const int col = cn0 + nb + nf * 8 + 2 * tg;
            float2 v0, v1_;
            v0.x  = fmaxf(acc[mf][nf][0] * sc0 + bp0, 0.f);
            v0.y  = fmaxf(acc[mf][nf][1] * sc0 + bp0, 0.f);
            v1_.x = fmaxf(acc[mf][nf][2] * sc1 + bp1, 0.f);
            v1_.y = fmaxf(acc[mf][nf][3] * sc1 + bp1, 0.f);
            *(float2*)&g_tp[b][o0][col] = v0;
            *(float2*)&g_tp[b][o1][col] = v1_;
            const float wA = wsel[col - cn0 + cn0];        // wsel[col]
            const float wBv = wsel[col + 1];
            up0 += wA * v0.x + wBv * v0.y;
            up1 += wA * v1_.x + wBv * v1_.y;
        }
        up0 += __shfl_xor_sync(0xffffffffu, up0, 1);
        up0 += __shfl_xor_sync(0xffffffffu, up0, 2);
        up1 += __shfl_xor_sync(0xffffffffu, up1, 1);
        up1 += __shfl_xor_sync(0xffffffffu, up1, 2);
        if (tg == 0) {
            g_uvpart[b][o0][slot] = up0;
            g_uvpart[b][o1][slot] = up1;
        }
    }
}

// ---------------------------------------------------------------------------
// K4: conv3 GEMM (3-term bf16) + BN + ReLU + partial hw-pool.
// grid (hw=8, o=4, b=32), 256 threads.
// ---------------------------------------------------------------------------
__global__ __launch_bounds__(256) void k_mma_xe(
    const float* __restrict__ b3, const float* __restrict__ g3,
    const float* __restrict__ be3, const float* __restrict__ m3,
    const float* __restrict__ v3)
{
    const uint32_t* smw = dynw;
    const uint32_t sb = smem_u32(smw);
    const int tid = threadIdx.x, lane = tid & 31, w = tid >> 5;
    const int mw = w & 1, nw = w >> 1;
    const int g = lane >> 2, tg = lane & 3;
    const int mb = mw * 64, nb = nw * 32;
    const int b = blockIdx.z, om0 = blockIdx.y * 128, n0 = blockIdx.x * 128;

    float acc[4][4][4];
    #pragma unroll
    for (int i = 0; i < 4; i++)
        #pragma unroll
        for (int j = 0; j < 4; j++)
            #pragma unroll
            for (int q = 0; q < 4; q++) acc[i][j][q] = 0.f;

    const __nv_bfloat16* Ah = g_w3hi + (size_t)om0 * NC;
    const __nv_bfloat16* Al = g_w3lo + (size_t)om0 * NC;
    const __nv_bfloat16* Bh = g_xThi + ((size_t)b * NHW + n0) * NC;
    const __nv_bfloat16* Bl = g_xTlo + ((size_t)b * NHW + n0) * NC;

    gemm_main<NC / BKF>(sb, smw, Ah, Al, NC, Bh, Bl, NC, tid, mb, nb, g, tg, acc);

    #pragma unroll
    for (int mf = 0; mf < 4; mf++) {
        const int o0 = om0 + mb + mf * 16 + g;
        const int o1 = o0 + 8;
        const float sc0 = g3[o0] * rsqrtf(v3[o0] + EPSV);
        const float bp0 = (b3[o0] - m3[o0]) * sc0 + be3[o0];
        const float sc1 = g3[o1] * rsqrtf(v3[o1] + EPSV);
        const float bp1 = (b3[o1] - m3[o1]) * sc1 + be3[o1];
        float s0 = 0.f, s1 = 0.f;
        #pragma unroll
        for (int nf = 0; nf < 4; nf++) {
            s0 += fmaxf(acc[mf][nf][0] * sc0 + bp0, 0.f)
                + fmaxf(acc[mf][nf][1] * sc0 + bp0, 0.f);
            s1 += fmaxf(acc[mf][nf][2] * sc1 + bp1, 0.f)
                + fmaxf(acc[mf][nf][3] * sc1 + bp1, 0.f);
        }
        s0 += __shfl_xor_sync(0xffffffffu, s0, 1);
        s0 += __shfl_xor_sync(0xffffffffu, s0, 2);
        s1 += __shfl_xor_sync(0xffffffffu, s1, 1);
        s1 += __shfl_xor_sync(0xffffffffu, s1, 2);
        if (tg == 0) {
            g_xepart[b][o0][blockIdx.x * 4 + nw] = s0;
            g_xepart[b][o1][blockIdx.x * 4 + nw] = s1;
        }
    }
}

// ---------------------------------------------------------------------------
// K3: contrib partials.  coef[o] = sum slots of paired row (o XOR 256).
// grid (p=4, oc=8, b=32), 128 threads.
// ---------------------------------------------------------------------------
__global__ __launch_bounds__(128) void k_contrib()
{
    const int b = blockIdx.z, oc = blockIdx.y;
    const int p0 = blockIdx.x * 128, o0 = oc * 64;
    const int t = threadIdx.x;
    __shared__ float coef[64];
    if (t < 64) {
        const int src = (o0 + t) ^ 256;
        float s = 0.f;
        #pragma unroll
        for (int j = 0; j < 16; j++) s += g_uvpart[b][src][j];
        coef[t] = s;
    }
    __syncthreads();
    float acc = 0.f;
    const int p = p0 + t;
    #pragma unroll 8
    for (int o = 0; o < 64; o++)
        acc += coef[o] * g_tp[b][o0 + o][p];
    g_cpart[b][p][oc] = acc;
}

// ---------------------------------------------------------------------------
// K5: logits -> sigmoid -> out = x * gate
// ---------------------------------------------------------------------------
__global__ __launch_bounds__(256) void k_final(
    const float* __restrict__ x, const float* __restrict__ w4,
    const float* __restrict__ b4, float* __restrict__ out)
{
    const int bp = blockIdx.x;
    const int b = bp >> 9, p = bp & 511;
    float s = 0.f;
    #pragma unroll
    for (int j = 0; j < 32; j++) s += g_xepart[b][p][j];
    float cs = 0.f;
    #pragma unroll
    for (int j = 0; j < 8; j++) cs += g_cpart[b][p][j];
    const float xe = s * (1.f / 1024.f);
    const float logit = w4[0] * xe + cs + b4[0];
    const float gate = 1.f / (1.f + expf(-logit));
    const float4* xi = (const float4*)(x + (size_t)bp * NHW);
    float4*       oo = (float4*)(out + (size_t)bp * NHW);
    float4 v = xi[threadIdx.x];
    v.x *= gate; v.y *= gate; v.z *= gate; v.w *= gate;
    oo[threadIdx.x] = v;
}

// ---------------------------------------------------------------------------
extern "C" void kernel_launch(void* const* d_in, const int* in_sizes, int n_in,
                              void* d_out, int out_size)
{
    const float* x   = (const float*)d_in[0];
    const float* w1  = (const float*)d_in[1];
    const float* b1  = (const float*)d_in[2];
    const float* g1  = (const float*)d_in[3];
    const float* be1 = (const float*)d_in[4];
    const float* m1  = (const float*)d_in[5];
    const float* v1  = (const float*)d_in[6];
    const float* w2  = (const float*)d_in[7];
    const float* b2  = (const float*)d_in[8];
    const float* g2  = (const float*)d_in[9];
    const float* be2 = (const float*)d_in[10];
    const float* m2  = (const float*)d_in[11];
    const float* v2  = (const float*)d_in[12];
    const float* w3  = (const float*)d_in[13];
    const float* b3  = (const float*)d_in[14];
    const float* g3  = (const float*)d_in[15];
    const float* be3 = (const float*)d_in[16];
    const float* m3  = (const float*)d_in[17];
    const float* v3  = (const float*)d_in[18];
    const float* w4  = (const float*)d_in[19];
    const float* b4  = (const float*)d_in[20];
    float* out = (float*)d_out;

    cudaFuncSetAttribute(k_mma_tp, cudaFuncAttributeMaxDynamicSharedMemorySize, SMEM_BYTES);
    cudaFuncSetAttribute(k_mma_xe, cudaFuncAttributeMaxDynamicSharedMemorySize, SMEM_BYTES);

    k_split_w<<<(2*NOUT*NHW + NC*NC + 255) / 256, 256>>>(w1, w2, w3);
    k_split_x<<<dim3(32, 16, NB), 256>>>(x);
    k_mma_tp<<<dim3(4, 4, NB), 256, SMEM_BYTES>>>(b1, g1, be1, m1, v1,
                                                  b2, g2, be2, m2, v2, w4);
    k_mma_xe<<<dim3(8, 4, NB), 256, SMEM_BYTES>>>(b3, g3, be3, m3, v3);
    k_contrib<<<dim3(4, 8, NB), 128>>>();
    k_final<<<NB * NC, 256>>>(x, w4, b4, out);
}

// round 16
// speedup vs baseline: 1.1156x; 1.1156x over previous
#include <cuda_runtime.h>
#include <cuda_bf16.h>
#include <math.h>
#include <stdint.h>

#define NB   32
#define NC   512
#define NHW  1024
#define NOUT 256
#define EPSV 1e-5f
#define BKF  32                  // K elements per stage
#define WB   20                  // SMEM words (4B) per 32-bf16 row (pad to 80B)
#define TILE_W (128 * WB)        // 2560 words per 128xBKF bf16 tile
#define BUF_W  (4 * TILE_W)      // Ahi,Alo,Bhi,Blo per stage buffer
#define SMEM_BYTES (2 * BUF_W * 4)   // 81920 B

// ----------------------------- scratch -------------------------------------
__device__ float g_tp[NB][2*NOUT][NC];          // theta [0,256), phi [256,512)
__device__ float g_uvpart[NB][2*NOUT][16];      // w4-weighted row partials
__device__ float g_xepart[NB][NC][32];
__device__ float g_cpart[NB][NC][8];
__device__ __nv_bfloat16 g_xhi[(size_t)NB*NC*NHW];   // x split, [b][c][hw]
__device__ __nv_bfloat16 g_xlo[(size_t)NB*NC*NHW];
__device__ __nv_bfloat16 g_xThi[(size_t)NB*NHW*NC];  // x^T split, [b][hw][c]
__device__ __nv_bfloat16 g_xTlo[(size_t)NB*NHW*NC];
__device__ __nv_bfloat16 g_w12hi[2*NOUT*NHW];        // concat(w1,w2) split
__device__ __nv_bfloat16 g_w12lo[2*NOUT*NHW];
__device__ __nv_bfloat16 g_w3hi[NC*NC];
__device__ __nv_bfloat16 g_w3lo[NC*NC];

extern __shared__ uint32_t dynw[];

// ----------------------------- PTX helpers ---------------------------------
__device__ __forceinline__ uint32_t smem_u32(const void* p) {
    uint32_t a;
    asm("{ .reg .u64 t; cvta.to.shared.u64 t, %1; cvt.u32.u64 %0, t; }" : "=r"(a) : "l"(p));
    return a;
}
__device__ __forceinline__ void cpa16(uint32_t dst, const void* src) {
    asm volatile("cp.async.cg.shared.global [%0], [%1], 16;" :: "r"(dst), "l"(src));
}
__device__ __forceinline__ void cpa_commit() { asm volatile("cp.async.commit_group;"); }
template<int N> __device__ __forceinline__ void cpa_wait() {
    asm volatile("cp.async.wait_group %0;" :: "n"(N));
}
// D(16x8) += A(16x16) * B^T, bf16 inputs, fp32 accum
__device__ __forceinline__ void mma16(float* c, const uint32_t* a, const uint32_t* b) {
    asm volatile("mma.sync.aligned.m16n8k16.row.col.f32.bf16.bf16.f32 "
        "{%0,%1,%2,%3}, {%4,%5,%6,%7}, {%8,%9}, {%0,%1,%2,%3};"
        : "+f"(c[0]), "+f"(c[1]), "+f"(c[2]), "+f"(c[3])
        : "r"(a[0]), "r"(a[1]), "r"(a[2]), "r"(a[3]), "r"(b[0]), "r"(b[1]));
}
__device__ __forceinline__ void ldsm4(uint32_t* r, uint32_t addr) {
    asm volatile("ldmatrix.sync.aligned.m8n8.x4.shared.b16 {%0,%1,%2,%3}, [%4];"
        : "=r"(r[0]), "=r"(r[1]), "=r"(r[2]), "=r"(r[3]) : "r"(addr));
}
__device__ __forceinline__ void split2(float a, float b,
                                       __nv_bfloat162& h, __nv_bfloat162& l) {
    __nv_bfloat16 ha = __float2bfloat16(a), hb = __float2bfloat16(b);
    __nv_bfloat16 la = __float2bfloat16(a - __bfloat162float(ha));
    __nv_bfloat16 lb = __float2bfloat16(b - __bfloat162float(hb));
    h = __halves2bfloat162(ha, hb);
    l = __halves2bfloat162(la, lb);
}

// Async-copy a 128x32 bf16 tile (row stride ld elems) into padded SMEM tile.
__device__ __forceinline__ void load_tile_bf(uint32_t sb, int woff,
        const __nv_bfloat16* __restrict__ src, int ld, int k0, int tid) {
    #pragma unroll
    for (int i = 0; i < 2; i++) {
        const int c = tid + i * 256;      // 512 chunks of 16B
        const int row = c >> 2;
        const int q = c & 3;
        cpa16(sb + (uint32_t)(woff + row * WB) * 4u + q * 16,
              src + (size_t)row * ld + k0 + q * 8);
    }
}

// One BK=32 stage: 3-term bf16 MMAs fed by ldmatrix.x4.
// aHi/aLo/bHi/bLo are this-buffer, this-lane byte addresses (tile bases).
__device__ __forceinline__ void stage_mma(uint32_t aHi, uint32_t aLo,
                                          uint32_t bHi, uint32_t bLo,
                                          float (&acc)[4][4][4]) {
    #pragma unroll
    for (int ks = 0; ks < 2; ks++) {
        const uint32_t kb = (uint32_t)(ks * 8) * 4;
        // B: pair p covers nf=2p,2p+1 -> regs {b[2p][0],b[2p][1],b[2p+1][0],b[2p+1][1]}
        uint32_t bh[2][4], bl[2][4];
        ldsm4(bh[0], bHi + kb);
        ldsm4(bh[1], bHi + kb + (uint32_t)(16 * WB) * 4);
        ldsm4(bl[0], bLo + kb);
        ldsm4(bl[1], bLo + kb + (uint32_t)(16 * WB) * 4);
        #pragma unroll
        for (int mf = 0; mf < 4; mf++) {
            const uint32_t mo = kb + (uint32_t)(mf * 16 * WB) * 4;
            uint32_t ah[4], al[4];
            ldsm4(ah, aHi + mo);
            ldsm4(al, aLo + mo);
            #pragma unroll
            for (int nf = 0; nf < 4; nf++) {
                const uint32_t* bhp = &bh[nf >> 1][(nf & 1) * 2];
                const uint32_t* blp = &bl[nf >> 1][(nf & 1) * 2];
                mma16(acc[mf][nf], ah, bhp);
                mma16(acc[mf][nf], ah, blp);
                mma16(acc[mf][nf], al, bhp);
            }
        }
    }
}

// Double-buffered mainloop: D[128,128] += A[128,K] * B[128,K]^T
template<int KSTEPS>
__device__ __forceinline__ void gemm_main(uint32_t sb,
        const __nv_bfloat16* __restrict__ Ahi, const __nv_bfloat16* __restrict__ Alo, int lda,
        const __nv_bfloat16* __restrict__ Bhi, const __nv_bfloat16* __restrict__ Blo, int ldb,
        int tid, int mb, int nb, float (&acc)[4][4][4]) {
    // ldmatrix lane base addresses (tile-relative, in bytes)
    const int l = tid & 31;
    const uint32_t aoff = (uint32_t)((mb + (l & 15)) * WB + ((l >> 4) << 2)) * 4;
    const uint32_t boff = (uint32_t)((nb + ((l >> 4) << 3) + (l & 7)) * WB
                                     + (((l >> 3) & 1) << 2)) * 4;

    load_tile_bf(sb, 0,          Ahi, lda, 0, tid);
    load_tile_bf(sb, TILE_W,     Alo, lda, 0, tid);
    load_tile_bf(sb, 2 * TILE_W, Bhi, ldb, 0, tid);
    load_tile_bf(sb, 3 * TILE_W, Blo, ldb, 0, tid);
    cpa_commit();
    for (int s = 0; s < KSTEPS; s++) {
        const int cur = s & 1;
        if (s + 1 < KSTEPS) {
            const int nw_ = ((s + 1) & 1) * BUF_W;
            const int k1 = (s + 1) * BKF;
            load_tile_bf(sb, nw_,              Ahi, lda, k1, tid);
            load_tile_bf(sb, nw_ + TILE_W,     Alo, lda, k1, tid);
            load_tile_bf(sb, nw_ + 2 * TILE_W, Bhi, ldb, k1, tid);
            load_tile_bf(sb, nw_ + 3 * TILE_W, Blo, ldb, k1, tid);
            cpa_commit();
            cpa_wait<1>();
        } else {
            cpa_wait<0>();
        }
        __syncthreads();
        const uint32_t base = sb + (uint32_t)(cur * BUF_W) * 4;
        stage_mma(base + aoff,
                  base + (uint32_t)TILE_W * 4 + aoff,
                  base + (uint32_t)(2 * TILE_W) * 4 + boff,
                  base + (uint32_t)(3 * TILE_W) * 4 + boff,
                  acc);
        __syncthreads();
    }
}

// ---------------------------------------------------------------------------
// P0: split weights into bf16 hi/lo
// ---------------------------------------------------------------------------
__global__ __launch_bounds__(256) void k_split_w(
    const float* __restrict__ w1, const float* __restrict__ w2,
    const float* __restrict__ w3)
{
    const int idx = blockIdx.x * 256 + threadIdx.x;
    const int N12 = 2 * NOUT * NHW;                  // 524288
    if (idx < N12) {
        float v = (idx < NOUT * NHW) ? w1[idx] : w2[idx - NOUT * NHW];
        __nv_bfloat16 h = __float2bfloat16(v);
        g_w12hi[idx] = h;
        g_w12lo[idx] = __float2bfloat16(v - __bfloat162float(h));
    } else {
        const int j = idx - N12;
        if (j < NC * NC) {
            float v = w3[j];
            __nv_bfloat16 h = __float2bfloat16(v);
            g_w3hi[j] = h;
            g_w3lo[j] = __float2bfloat16(v - __bfloat162float(h));
        }
    }
}

// ---------------------------------------------------------------------------
// P1: split x into bf16 hi/lo in BOTH layouts ([c][hw] and [hw][c])
// ---------------------------------------------------------------------------
__global__ __launch_bounds__(256) void k_split_x(const float* __restrict__ x)
{
    __shared__ float t[32][33];
    const int b = blockIdx.z;
    const int h0 = blockIdx.x * 32, c0 = blockIdx.y * 32;
    const int tid = threadIdx.x;
    const int tx = tid & 31, ty = tid >> 5;
    #pragma unroll
    for (int i = 0; i < 4; i++) {
        const int r = ty + i * 8;
        t[r][tx] = x[((size_t)b * NC + c0 + r) * NHW + h0 + tx];
    }
    __syncthreads();
    const int jr = tid >> 4;      // 0..15
    const int jc = tid & 15;      // pair index
    #pragma unroll
    for (int pass = 0; pass < 2; pass++) {
        const int r = jr + pass * 16;
        {
            __nv_bfloat162 h, l;
            split2(t[r][2*jc], t[r][2*jc + 1], h, l);
            const size_t base = (((size_t)b * NC + c0 + r) * NHW + h0) >> 1;
            ((__nv_bfloat162*)g_xhi)[base + jc] = h;
            ((__nv_bfloat162*)g_xlo)[base + jc] = l;
        }
        {
            __nv_bfloat162 h, l;
            split2(t[2*jc][r], t[2*jc + 1][r], h, l);
            const size_t base = (((size_t)b * NHW + h0 + r) * NC + c0) >> 1;
            ((__nv_bfloat162*)g_xThi)[base + jc] = h;
            ((__nv_bfloat162*)g_xTlo)[base + jc] = l;
        }
    }
}

// ---------------------------------------------------------------------------
// K1: theta/phi GEMM (3-term bf16) + BN + ReLU + fused u/v partials.
// grid (cn=4, om=4, b=32), 256 threads.
// ---------------------------------------------------------------------------
__global__ __launch_bounds__(256, 2) void k_mma_tp(
    const float* __restrict__ b1, const float* __restrict__ g1,
    const float* __restrict__ be1, const float* __restrict__ m1,
    const float* __restrict__ v1,
    const float* __restrict__ b2, const float* __restrict__ g2,
    const float* __restrict__ be2, const float* __restrict__ m2,
    const float* __restrict__ v2, const float* __restrict__ w4)
{
    const uint32_t sb = smem_u32(dynw);
    const int tid = threadIdx.x, lane = tid & 31, w = tid >> 5;
    const int mw = w & 1, nw = w >> 1;
    const int g = lane >> 2, tg = lane & 3;
    const int mb = mw * 64, nb = nw * 32;
    const int b = blockIdx.z, om0 = blockIdx.y * 128, cn0 = blockIdx.x * 128;

    float acc[4][4][4];
    #pragma unroll
    for (int i = 0; i < 4; i++)
        #pragma unroll
        for (int j = 0; j < 4; j++)
            #pragma unroll
            for (int q = 0; q < 4; q++) acc[i][j][q] = 0.f;

    const __nv_bfloat16* Ah = g_w12hi + (size_t)om0 * NHW;
    const __nv_bfloat16* Al = g_w12lo + (size_t)om0 * NHW;
    const __nv_bfloat16* Bh = g_xhi + ((size_t)b * NC + cn0) * NHW;
    const __nv_bfloat16* Bl = g_xlo + ((size_t)b * NC + cn0) * NHW;

    gemm_main<NHW / BKF>(sb, Ah, Al, NHW, Bh, Bl, NHW, tid, mb, nb, acc);

    // w4 weight for u/v partial: theta rows -> w4[1+NC+c] (v), phi rows -> w4[1+c] (u)
    const float* wsel = (om0 < NOUT) ? (w4 + 1 + NC) : (w4 + 1);
    const int slot = blockIdx.x * 4 + nw;

    #pragma unroll
    for (int mf = 0; mf < 4; mf++) {
        const int o0 = om0 + mb + mf * 16 + g;
        const int o1 = o0 + 8;
        float sc0, bp0, sc1, bp1;
        if (om0 < NOUT) {
            sc0 = g1[o0] * rsqrtf(v1[o0] + EPSV);
            bp0 = (b1[o0] - m1[o0]) * sc0 + be1[o0];
            sc1 = g1[o1] * rsqrtf(v1[o1] + EPSV);
            bp1 = (b1[o1] - m1[o1]) * sc1 + be1[o1];
        } else {
            const int p0 = o0 - NOUT, p1 = o1 - NOUT;
            sc0 = g2[p0] * rsqrtf(v2[p0] + EPSV);
            bp0 = (b2[p0] - m2[p0]) * sc0 + be2[p0];
            sc1 = g2[p1] * rsqrtf(v2[p1] + EPSV);
            bp1 = (b2[p1] - m2[p1]) * sc1 + be2[p1];
        }
        float up0 = 0.f, up1 = 0.f;
        #pragma unroll
        for (int nf = 0; nf < 4; nf++) {
            const int col = cn0 + nb + nf * 8 + 2 * tg;
            float2 v0, v1_;
            v0.x  = fmaxf(acc[mf][nf][0] * sc0 + bp0, 0.f);
            v0.y  = fmaxf(acc[mf][nf][1] * sc0 + bp0, 0.f);
            v1_.x = fmaxf(acc[mf][nf][2] * sc1 + bp1, 0.f);
            v1_.y = fmaxf(acc[mf][nf][3] * sc1 + bp1, 0.f);
            *(float2*)&g_tp[b][o0][col] = v0;
            *(float2*)&g_tp[b][o1][col] = v1_;
            const float wA  = wsel[col];
            const float wBv = wsel[col + 1];
            up0 += wA * v0.x + wBv * v0.y;
            up1 += wA * v1_.x + wBv * v1_.y;
        }
        up0 += __shfl_xor_sync(0xffffffffu, up0, 1);
        up0 += __shfl_xor_sync(0xffffffffu, up0, 2);
        up1 += __shfl_xor_sync(0xffffffffu, up1, 1);
        up1 += __shfl_xor_sync(0xffffffffu, up1, 2);
        if (tg == 0) {
            g_uvpart[b][o0][slot] = up0;
            g_uvpart[b][o1][slot] = up1;
        }
    }
}

// ---------------------------------------------------------------------------
// K4: conv3 GEMM (3-term bf16) + BN + ReLU + partial hw-pool.
// grid (hw=8, o=4, b=32), 256 threads.
// ---------------------------------------------------------------------------
__global__ __launch_bounds__(256, 2) void k_mma_xe(
    const float* __restrict__ b3, const float* __restrict__ g3,
    const float* __restrict__ be3, const float* __restrict__ m3,
    const float* __restrict__ v3)
{
    const uint32_t sb = smem_u32(dynw);
    const int tid = threadIdx.x, lane = tid & 31, w = tid >> 5;
    const int mw = w & 1, nw = w >> 1;
    const int g = lane >> 2, tg = lane & 3;
    const int mb = mw * 64, nb = nw * 32;
    const int b = blockIdx.z, om0 = blockIdx.y * 128, n0 = blockIdx.x * 128;
    (void)tg;

    float acc[4][4][4];
    #pragma unroll
    for (int i = 0; i < 4; i++)
        #pragma unroll
        for (int j = 0; j < 4; j++)
            #pragma unroll
            for (int q = 0; q < 4; q++) acc[i][j][q] = 0.f;

    const __nv_bfloat16* Ah = g_w3hi + (size_t)om0 * NC;
    const __nv_bfloat16* Al = g_w3lo + (size_t)om0 * NC;
    const __nv_bfloat16* Bh = g_xThi + ((size_t)b * NHW + n0) * NC;
    const __nv_bfloat16* Bl = g_xTlo + ((size_t)b * NHW + n0) * NC;

    gemm_main<NC / BKF>(sb, Ah, Al, NC, Bh, Bl, NC, tid, mb, nb, acc);

    #pragma unroll
    for (int mf = 0; mf < 4; mf++) {
        const int o0 = om0 + mb + mf * 16 + g;
        const int o1 = o0 + 8;
        const float sc0 = g3[o0] * rsqrtf(v3[o0] + EPSV);
        const float bp0 = (b3[o0] - m3[o0]) * sc0 + be3[o0];
        const float sc1 = g3[o1] * rsqrtf(v3[o1] + EPSV);
        const float bp1 = (b3[o1] - m3[o1]) * sc1 + be3[o1];
        float s0 = 0.f, s1 = 0.f;
        #pragma unroll
        for (int nf = 0; nf < 4; nf++) {
            s0 += fmaxf(acc[mf][nf][0] * sc0 + bp0, 0.f)
                + fmaxf(acc[mf][nf][1] * sc0 + bp0, 0.f);
            s1 += fmaxf(acc[mf][nf][2] * sc1 + bp1, 0.f)
                + fmaxf(acc[mf][nf][3] * sc1 + bp1, 0.f);
        }
        s0 += __shfl_xor_sync(0xffffffffu, s0, 1);
        s0 += __shfl_xor_sync(0xffffffffu, s0, 2);
        s1 += __shfl_xor_sync(0xffffffffu, s1, 1);
        s1 += __shfl_xor_sync(0xffffffffu, s1, 2);
        if ((lane & 3) == 0) {
            g_xepart[b][o0][blockIdx.x * 4 + nw] = s0;
            g_xepart[b][o1][blockIdx.x * 4 + nw] = s1;
        }
    }
}

// ---------------------------------------------------------------------------
// K3: contrib partials.  coef[o] = sum slots of paired row (o XOR 256).
// grid (p=4, oc=8, b=32), 128 threads.
// ---------------------------------------------------------------------------
__global__ __launch_bounds__(128) void k_contrib()
{
    const int b = blockIdx.z, oc = blockIdx.y;
    const int p0 = blockIdx.x * 128, o0 = oc * 64;
    const int t = threadIdx.x;
    __shared__ float coef[64];
    if (t < 64) {
        const int src = (o0 + t) ^ 256;
        float s = 0.f;
        #pragma unroll
        for (int j = 0; j < 16; j++) s += g_uvpart[b][src][j];
        coef[t] = s;
    }
    __syncthreads();
    float acc = 0.f;
    const int p = p0 + t;
    #pragma unroll 8
    for (int o = 0; o < 64; o++)
        acc += coef[o] * g_tp[b][o0 + o][p];
    g_cpart[b][p][oc] = acc;
}

// ---------------------------------------------------------------------------
// K5: logits -> sigmoid -> out = x * gate
// ---------------------------------------------------------------------------
__global__ __launch_bounds__(256) void k_final(
    const float* __restrict__ x, const float* __restrict__ w4,
    const float* __restrict__ b4, float* __restrict__ out)
{
    const int bp = blockIdx.x;
    const int b = bp >> 9, p = bp & 511;
    float s = 0.f;
    #pragma unroll
    for (int j = 0; j < 32; j++) s += g_xepart[b][p][j];
    float cs = 0.f;
    #pragma unroll
    for (int j = 0; j < 8; j++) cs += g_cpart[b][p][j];
    const float xe = s * (1.f / 1024.f);
    const float logit = w4[0] * xe + cs + b4[0];
    const float gate = 1.f / (1.f + expf(-logit));
    const float4* xi = (const float4*)(x + (size_t)bp * NHW);
    float4*       oo = (float4*)(out + (size_t)bp * NHW);
    float4 v = xi[threadIdx.x];
    v.x *= gate; v.y *= gate; v.z *= gate; v.w *= gate;
    oo[threadIdx.x] = v;
}

// ---------------------------------------------------------------------------
extern "C" void kernel_launch(void* const* d_in, const int* in_sizes, int n_in,
                              void* d_out, int out_size)
{
    const float* x   = (const float*)d_in[0];
    const float* w1  = (const float*)d_in[1];
    const float* b1  = (const float*)d_in[2];
    const float* g1  = (const float*)d_in[3];
    const float* be1 = (const float*)d_in[4];
    const float* m1  = (const float*)d_in[5];
    const float* v1  = (const float*)d_in[6];
    const float* w2  = (const float*)d_in[7];
    const float* b2  = (const float*)d_in[8];
    const float* g2  = (const float*)d_in[9];
    const float* be2 = (const float*)d_in[10];
    const float* m2  = (const float*)d_in[11];
    const float* v2  = (const float*)d_in[12];
    const float* w3  = (const float*)d_in[13];
    const float* b3  = (const float*)d_in[14];
    const float* g3  = (const float*)d_in[15];
    const float* be3 = (const float*)d_in[16];
    const float* m3  = (const float*)d_in[17];
    const float* v3  = (const float*)d_in[18];
    const float* w4  = (const float*)d_in[19];
    const float* b4  = (const float*)d_in[20];
    float* out = (float*)d_out;

    cudaFuncSetAttribute(k_mma_tp, cudaFuncAttributeMaxDynamicSharedMemorySize, SMEM_BYTES);
    cudaFuncSetAttribute(k_mma_xe, cudaFuncAttributeMaxDynamicSharedMemorySize, SMEM_BYTES);

    k_split_w<<<(2*NOUT*NHW + NC*NC + 255) / 256, 256>>>(w1, w2, w3);
    k_split_x<<<dim3(32, 16, NB), 256>>>(x);
    k_mma_tp<<<dim3(4, 4, NB), 256, SMEM_BYTES>>>(b1, g1, be1, m1, v1,
                                                  b2, g2, be2, m2, v2, w4);
    k_mma_xe<<<dim3(8, 4, NB), 256, SMEM_BYTES>>>(b3, g3, be3, m3, v3);
    k_contrib<<<dim3(4, 8, NB), 128>>>();
    k_final<<<NB * NC, 256>>>(x, w4, b4, out);
}